// round 6
// baseline (speedup 1.0000x reference)
#include <cuda_runtime.h>
#include <cstdint>
#include <math.h>

#define PLANE 19660800ll
#define ITERS 1280
#define STGB  16384
#define SMEMSZ (4*STGB + 1024)

// packed fp16 B tiles: [jt 0..3][chunk 0..1279][16KB SW128 tile image]
__device__ uint8_t g_wp[4ull*1280ull*16384ull];

static __device__ __forceinline__ uint32_t s2u(const void* p){
    uint32_t a;
    asm("{ .reg .u64 t; cvta.to.shared.u64 t, %1; cvt.u32.u64 %0, t; }":"=r"(a):"l"(p));
    return a;
}
static __device__ __forceinline__ uint32_t cvt2(float s, float c){
    uint32_t r;  // lo = c (k even), hi = s (k odd)
    asm("cvt.rn.f16x2.f32 %0, %1, %2;" : "=r"(r) : "f"(s), "f"(c));
    return r;
}
static __device__ __forceinline__ void cp16(uint32_t dst, const void* src){
    asm volatile("cp.async.cg.shared.global [%0], [%1], 16;" :: "r"(dst), "l"(src) : "memory");
}
static __device__ __forceinline__ void ldsm4(uint32_t* r, uint32_t a){
    asm volatile("ldmatrix.sync.aligned.m8n8.x4.shared.b16 {%0,%1,%2,%3}, [%4];"
        : "=r"(r[0]), "=r"(r[1]), "=r"(r[2]), "=r"(r[3]) : "r"(a));
}
static __device__ __forceinline__ void mma16(float* d, const uint32_t* a, uint32_t b0, uint32_t b1){
    asm volatile("mma.sync.aligned.m16n8k16.row.col.f32.f16.f16.f32 "
        "{%0,%1,%2,%3}, {%4,%5,%6,%7}, {%8,%9}, {%0,%1,%2,%3};"
        : "+f"(d[0]), "+f"(d[1]), "+f"(d[2]), "+f"(d[3])
        : "r"(a[0]), "r"(a[1]), "r"(a[2]), "r"(a[3]), "r"(b0), "r"(b1));
}

// ---------- repack: fp32 coeffs -> fp16 pre-swizzled SW128 tile images (+eps sign) ----------
__global__ void __launch_bounds__(256) kan_repack(const float* __restrict__ cf){
    uint32_t t  = blockIdx.x * 256u + threadIdx.x;   // 20,971,520 words
    uint32_t w  = t & 31u;                           // k-pair word within row
    uint32_t n  = (t >> 5) & 127u;                   // row (output feature in tile)
    uint32_t rest = t >> 12;
    uint32_t cch = rest % 1280u;                     // chunk
    uint32_t jt  = rest / 1280u;                     // N tile
    uint32_t p = cch * 32u + w;                      // global pair index
    uint32_t i = p / 320u;
    uint32_t g = p - i * 320u;                       // pair index in i-block (freq g+1)
    uint32_t j = jt * 128u + n;
    float v0 = 0.f, v1 = 0.f;
    if (g < 300u){
        size_t ix = ((size_t)j * 128 + i) * 300 + g;
        v0 = cf[ix];            // cos coeff -> lo
        v1 = cf[PLANE + ix];    // sin coeff -> hi
    }
    if (((g >> 2) & 3u) >= 2u){ v0 = -v0; v1 = -v1; }   // fold eps sign of A-chain
    uint32_t word;
    asm("cvt.rn.f16x2.f32 %0, %1, %2;" : "=r"(word) : "f"(v1), "f"(v0));
    uint32_t off = n * 128u + w * 4u;
    off ^= (off >> 3) & 0x70u;                       // SW128 pre-swizzle
    *(uint32_t*)(g_wp + ((size_t)(jt * 1280u + cch) << 14) + off) = word;
}

// ---------- GEMM: A generated in-register (Chebyshev stride-4), B via cp.async, mma.sync ----------
__global__ void __launch_bounds__(256,1) kan_gemm(const float* __restrict__ x, float* __restrict__ out){
    extern __shared__ uint8_t dsm[];
    uint32_t stg0 = (s2u(dsm) + 1023u) & ~1023u;
    int tid = threadIdx.x, l = tid & 31, w = tid >> 5;
    int wm = w & 3, wn = w >> 2;                      // warp grid 4(M) x 2(N)
    int mt = blockIdx.x >> 2, jt = blockIdx.x & 3;
    int p0 = l & 3;
    const uint8_t* wsrc = g_wp + ((size_t)jt * 1280u << 14);

    float acc[2][8][4];
    #pragma unroll
    for (int a = 0; a < 2; ++a)
        #pragma unroll
        for (int b = 0; b < 8; ++b)
            #pragma unroll
            for (int c = 0; c < 4; ++c) acc[a][b][c] = 0.f;

    float cP[4], cC[4], sP[4], sC[4], t2[4];          // 4 row-chains per lane

    // prologue: 3 stages in flight
    #pragma unroll
    for (int s = 0; s < 3; ++s){
        #pragma unroll
        for (int q = 0; q < 4; ++q)
            cp16(stg0 + s*STGB + tid*64 + q*16, wsrc + (size_t)s*STGB + tid*64 + q*16);
        asm volatile("cp.async.commit_group;" ::: "memory");
    }

    int imod = 0, icur = 0;
    for (int it = 0; it < ITERS; ++it){
        asm volatile("cp.async.wait_group 2;" ::: "memory");
        __syncthreads();
        {   int ns = it + 3;
            if (ns < ITERS){
                uint32_t d0 = stg0 + (ns & 3)*STGB + tid*64;
                const uint8_t* s0 = wsrc + ((size_t)ns)*STGB + tid*64;
                #pragma unroll
                for (int q = 0; q < 4; ++q) cp16(d0 + q*16, s0 + q*16);
            }
            asm volatile("cp.async.commit_group;" ::: "memory");
        }
        if (imod == 0){
            // reseed chains for new input feature i = icur
            #pragma unroll
            for (int c = 0; c < 4; ++c){
                int m = mt*128 + wm*32 + c*8 + (l >> 2);
                float xv = __ldg(x + (size_t)m*128 + icur);
                float s1, c1; sincosf(xv, &s1, &c1);
                float c2v = fmaf(2.f*c1, c1, -1.f), s2v = 2.f*c1*s1;
                float c3v = fmaf(2.f*c1, c2v, -c1), s3v = fmaf(2.f*c1, s2v, -s1);
                float c4v = fmaf(2.f*c1, c3v, -c2v), s4v = fmaf(2.f*c1, s3v, -s2v);
                t2[c] = 2.f*c4v;
                float Ac, As, Bc, Bs;
                if      (p0 == 0){ Ac=c1; As=s1; Bc=c3v; Bs=s3v; }
                else if (p0 == 1){ Ac=c2v; As=s2v; Bc=c2v; Bs=s2v; }
                else if (p0 == 2){ Ac=c3v; As=s3v; Bc=c1; Bs=s1; }
                else             { Ac=c4v; As=s4v; Bc=1.f; Bs=0.f; }
                cC[c] = Ac; sC[c] = As; cP[c] = -Bc; sP[c] = Bs;  // z_{-1} = -u_{-1}
            }
            imod = 10; icur++;
        }
        imod--;

        uint32_t sb = stg0 + (it & 3)*STGB;
        #pragma unroll
        for (int t = 0; t < 4; ++t){
            // B: 4x ldmatrix.x4 covering n64 x k16 for this warp column
            uint32_t bq[4][4];
            #pragma unroll
            for (int b = 0; b < 4; ++b){
                uint32_t nl = (uint32_t)(wn*64 + b*16 + (l & 7) + (((l >> 3) & 1) << 3));
                uint32_t ks = (uint32_t)(t*2 + (l >> 4));
                uint32_t off = nl*128u + ks*16u;
                off ^= (off >> 3) & 0x70u;
                ldsm4(bq[b], sb + off);
            }
            // A: advance 4 chains 2 steps, build two m16k16 frags
            uint32_t alo[4], ahi[4];
            #pragma unroll
            for (int c = 0; c < 4; ++c){
                alo[c] = cvt2(sC[c], cC[c]);
                float cn1 = fmaf( t2[c], cC[c], cP[c]);
                float sn1 = fmaf( t2[c], sC[c], sP[c]);
                ahi[c] = cvt2(sn1, cn1);
                float cn2 = fmaf(-t2[c], cn1, cC[c]);
                float sn2 = fmaf(-t2[c], sn1, sC[c]);
                cP[c] = cn1; cC[c] = cn2; sP[c] = sn1; sC[c] = sn2;
            }
            uint32_t af0[4] = {alo[0], alo[1], ahi[0], ahi[1]};
            uint32_t af1[4] = {alo[2], alo[3], ahi[2], ahi[3]};
            #pragma unroll
            for (int nf = 0; nf < 8; ++nf){
                uint32_t b0 = bq[nf >> 1][nf & 1], b1 = bq[nf >> 1][(nf & 1) + 2];
                mma16(acc[0][nf], af0, b0, b1);
                mma16(acc[1][nf], af1, b0, b1);
            }
        }
    }

    // epilogue: fp32 accum -> gmem
    #pragma unroll
    for (int mf = 0; mf < 2; ++mf){
        int r = mt*128 + wm*32 + mf*16 + (l >> 2);
        #pragma unroll
        for (int nf = 0; nf < 8; ++nf){
            int c = jt*128 + wn*64 + nf*8 + p0*2;
            float2 v0; v0.x = acc[mf][nf][0]; v0.y = acc[mf][nf][1];
            float2 v1; v1.x = acc[mf][nf][2]; v1.y = acc[mf][nf][3];
            *(float2*)(out + (size_t)r*512 + c)       = v0;
            *(float2*)(out + (size_t)(r+8)*512 + c)   = v1;
        }
    }
}

extern "C" void kernel_launch(void* const* d_in, const int* in_sizes, int n_in,
                              void* d_out, int out_size){
    const float* x  = (const float*)d_in[0];
    const float* cf = (const float*)d_in[1];
    kan_repack<<<81920, 256>>>(cf);
    cudaFuncSetAttribute(kan_gemm, cudaFuncAttributeMaxDynamicSharedMemorySize, SMEMSZ);
    kan_gemm<<<128, 256, SMEMSZ>>>(x, (float*)d_out);
}